// round 12
// baseline (speedup 1.0000x reference)
#include <cuda_runtime.h>
#include <math.h>

// x: 4096x4096 fp32 = 16,777,216 elems -> 262,144 blocks of 64.
// Single persistent kernel, 592 CTAs x 256 thr, 4 CTAs/SM resident
// (proven in R7/R9/R11) => one wave; spin grid-barrier is safe.
#define GRID  592
#define NT    7            // ceil(4194304 f4 / (592*1024)) = 7 tiles

__device__ float    g_pmin[GRID];
__device__ float    g_pmax[GRID];
__device__ float    g_smin;
__device__ float    g_ss;
__device__ int      g_cond;
__device__ unsigned g_ctr;            // phase-1 arrivals (returns to 0)
__device__ unsigned g_done;           // finishers       (returns to 0)
__device__ volatile unsigned g_flag;  // scales ready    (returns to 0)

// ---- Batcher selection pieces (fmax/fmin only: abs folds into FMNMX) ----
__device__ __forceinline__ void ce(float& a, float& b) {
    float hi = fmaxf(a, b);
    b = fminf(a, b);
    a = hi;
}
__device__ __forceinline__ void sort4(float& s0, float& s1, float& s2, float& s3) {
    ce(s0, s1); ce(s2, s3); ce(s0, s2); ce(s1, s3); ce(s1, s2);
}
// two sorted-desc-4 -> sorted-desc top-5 (13 ops)
__device__ __forceinline__ void merge44_top5(
    float a0, float a1, float a2, float a3,
    float b0, float b1, float b2, float b3,
    float& r0, float& r1, float& r2, float& r3, float& r4) {
    float e0 = fmaxf(a0, b0), x = fminf(a0, b0);
    float y  = fmaxf(a2, b2);
    float e1 = fmaxf(x, y),  e2 = fminf(x, y);
    float o0 = fmaxf(a1, b1), xp = fminf(a1, b1);
    float yp = fmaxf(a3, b3);
    float o1 = fmaxf(xp, yp);
    r0 = e0;
    r1 = fmaxf(o0, e1); r2 = fminf(o0, e1);
    r3 = fmaxf(o1, e2); r4 = fminf(o1, e2);
}
// two sorted-desc-5 -> sorted-desc top-5 (15 ops)
__device__ __forceinline__ void merge55_top5(
    float a0, float a1, float a2, float a3, float a4,
    float b0, float b1, float b2, float b3, float b4,
    float& r0, float& r1, float& r2, float& r3, float& r4) {
    float f0 = fmaxf(a0, b0), x = fminf(a0, b0);
    float y  = fmaxf(a4, b4);
    float f1 = fmaxf(x, y);
    float g0 = fmaxf(a2, b2);
    float e1 = fmaxf(g0, f1), e2 = fminf(g0, f1);
    float o0 = fmaxf(a1, b1), xp = fminf(a1, b1);
    float yp = fmaxf(a3, b3);
    float o1 = fmaxf(xp, yp);
    r0 = f0;
    r1 = fmaxf(o0, e1); r2 = fminf(o0, e1);
    r3 = fmaxf(o1, e2); r4 = fminf(o1, e2);
}
// two sorted-desc-5 -> ranks 3 & 4 only (10 ops)
__device__ __forceinline__ void merge55_r34(
    float a0, float a1, float a2, float a3, float a4,
    float b0, float b1, float b2, float b3, float b4,
    float& w3, float& w4) {
    float x  = fminf(a0, b0);
    float y  = fmaxf(a4, b4);
    float f1 = fmaxf(x, y);
    float g0 = fmaxf(a2, b2);
    float e2 = fminf(g0, f1);
    float xp = fminf(a1, b1);
    float yp = fmaxf(a3, b3);
    float o1 = fmaxf(xp, yp);
    w3 = fmaxf(o1, e2);
    w4 = fminf(o1, e2);
}

// quant+dequant one element (8 ops, proven): levels {0.75,1,1.5,2,3} are
// the 1-mantissa-bit fp32 grid -> clamp |q| to [0.75,3], +0x1FFFFF (round-
// half-down = positive argmin tie rule), mask. Zero if |q|<=0.375.
__device__ __forceinline__ float qd1(float x, float r, float deq) {
    float q = __fmul_rn(x, r);
    float a = fabsf(q);
    float m = fminf(fmaxf(a, 0.75f), 3.0f);
    unsigned u = (__float_as_uint(m) + 0x001FFFFFu) & 0xFFC00000u;
    float mag = (a > 0.375f) ? __uint_as_float(u) : 0.0f;
    float v = __fmul_rn(mag, deq);
    return __uint_as_float(__float_as_uint(v) |
                           (__float_as_uint(q) & 0x80000000u));
}

// XOR-swizzled slot within a warp's 128-f4 staging tile: row = f>>3 (128B),
// col = f&7 (16B granule), swizzled col = col ^ (row&7). Conflict-free for
// both the coalesced write (lane-contig f) and the 64B-stride read (f=4L+c).
__device__ __forceinline__ int sw(int f) {
    return (f & ~7) | ((f & 7) ^ ((f >> 3) & 7));
}

__global__ void __launch_bounds__(256, 4)
kFused(const float4* __restrict__ in4, float4* __restrict__ out4,
       int n4, int num_blocks) {
    __shared__ float4 sstage[8 * 128];   // 16KB: per-warp 2KB swizzled stage
    __shared__ float  ssc[NT][64];       // per-block scale s
    __shared__ float2 sinfo[NT][64];     // per-block {1/s, deq}
    __shared__ float  wmin[8], wmax[8];
    __shared__ float  rmin[256], rmax[256];
    __shared__ int    s_last;

    const int tid  = threadIdx.x;
    const int lane = tid & 31;
    const int warp = tid >> 5;
    const unsigned FULL = 0xFFFFFFFFu;

    float mn = 3.402823466e38f, mx = 0.0f;

    // ========== Phase 1: per-block scales (coalesced read via warp stage) ==
    #pragma unroll 1
    for (int t = 0; t < NT; t++) {
        int chunk = (t * GRID + blockIdx.x) * 1024;   // f4 base of CTA tile
        int wbase = chunk + warp * 128;               // warp covers 8 blocks

        __syncwarp();                                 // protect prior readers
        #pragma unroll
        for (int k = 0; k < 4; k++) {
            int f = k * 32 + lane;                    // coalesced: 512B/LDG
            int g = wbase + f;
            float4 v = (g < n4) ? __ldcg(&in4[g])
                                : make_float4(0.f, 0.f, 0.f, 0.f);
            sstage[warp * 128 + sw(f)] = v;
        }
        __syncwarp();

        float4 v0 = sstage[warp * 128 + sw(4 * lane + 0)];
        float4 v1 = sstage[warp * 128 + sw(4 * lane + 1)];
        float4 v2 = sstage[warp * 128 + sw(4 * lane + 2)];
        float4 v3 = sstage[warp * 128 + sw(4 * lane + 3)];

        float p0 = fabsf(v0.x), p1 = fabsf(v0.y), p2 = fabsf(v0.z), p3 = fabsf(v0.w);
        float q0 = fabsf(v1.x), q1 = fabsf(v1.y), q2 = fabsf(v1.z), q3 = fabsf(v1.w);
        float r0 = fabsf(v2.x), r1 = fabsf(v2.y), r2 = fabsf(v2.z), r3 = fabsf(v2.w);
        float u0 = fabsf(v3.x), u1 = fabsf(v3.y), u2 = fabsf(v3.z), u3 = fabsf(v3.w);
        sort4(p0, p1, p2, p3);
        sort4(q0, q1, q2, q3);
        sort4(r0, r1, r2, r3);
        sort4(u0, u1, u2, u3);

        float A0, A1, A2, A3, A4, B0, B1, B2, B3, B4;
        merge44_top5(p0, p1, p2, p3, q0, q1, q2, q3, A0, A1, A2, A3, A4);
        merge44_top5(r0, r1, r2, r3, u0, u1, u2, u3, B0, B1, B2, B3, B4);
        float t0, t1, t2, t3, t4;
        merge55_top5(A0, A1, A2, A3, A4, B0, B1, B2, B3, B4, t0, t1, t2, t3, t4);

        {   // cross-lane xor1: full sorted-5
            float b0 = __shfl_xor_sync(FULL, t0, 1);
            float b1 = __shfl_xor_sync(FULL, t1, 1);
            float b2 = __shfl_xor_sync(FULL, t2, 1);
            float b3 = __shfl_xor_sync(FULL, t3, 1);
            float b4 = __shfl_xor_sync(FULL, t4, 1);
            merge55_top5(t0, t1, t2, t3, t4, b0, b1, b2, b3, b4,
                         t0, t1, t2, t3, t4);
        }
        float w3, w4;
        {   // cross-lane xor2: only ranks 3 (4th largest) & 4 (5th largest)
            float b0 = __shfl_xor_sync(FULL, t0, 2);
            float b1 = __shfl_xor_sync(FULL, t1, 2);
            float b2 = __shfl_xor_sync(FULL, t2, 2);
            float b3 = __shfl_xor_sync(FULL, t3, 2);
            float b4 = __shfl_xor_sync(FULL, t4, 2);
            merge55_r34(t0, t1, t2, t3, t4, b0, b1, b2, b3, b4, w3, w4);
        }

        // jnp.quantile linear: a[59]*(1-frac)+a[60]*frac, frac=fp32(.95*63)-59
        const float FRAC = 0.95f * 63.0f - 59.0f;
        const float OMF  = 1.0f - FRAC;
        float s = __fadd_rn(__fmul_rn(w4, OMF), __fmul_rn(w3, FRAC));
        s = fmaxf(s, 1e-8f);
        if ((lane & 3) == 0) ssc[t][warp * 8 + (lane >> 2)] = s;

        int b = (chunk >> 4) + warp * 8 + (lane >> 2);
        if (b < num_blocks) { mn = fminf(mn, s); mx = fmaxf(mx, s); }
    }

    // CTA reduce min/max of scales
    #pragma unroll
    for (int m = 16; m > 0; m >>= 1) {
        mn = fminf(mn, __shfl_xor_sync(FULL, mn, m));
        mx = fmaxf(mx, __shfl_xor_sync(FULL, mx, m));
    }
    if (lane == 0) { wmin[warp] = mn; wmax[warp] = mx; }
    __syncthreads();
    if (tid == 0) {
        float cmn = wmin[0], cmx = wmax[0];
        #pragma unroll
        for (int k = 1; k < 8; k++) {
            cmn = fminf(cmn, wmin[k]);
            cmx = fmaxf(cmx, wmax[k]);
        }
        __stcg(&g_pmin[blockIdx.x], cmn);
        __stcg(&g_pmax[blockIdx.x], cmx);
        __threadfence();
        s_last = (atomicAdd(&g_ctr, 1u) == (unsigned)(gridDim.x - 1));
    }
    __syncthreads();

    // ========== Grid barrier: last CTA publishes smin/ss ===================
    if (s_last) {
        float fmn = 3.402823466e38f, fmx = 0.0f;
        for (int i = tid; i < GRID; i += 256) {
            fmn = fminf(fmn, __ldcg(&g_pmin[i]));
            fmx = fmaxf(fmx, __ldcg(&g_pmax[i]));
        }
        rmin[tid] = fmn; rmax[tid] = fmx;
        __syncthreads();
        #pragma unroll
        for (int off = 128; off > 0; off >>= 1) {
            if (tid < off) {
                rmin[tid] = fminf(rmin[tid], rmin[tid + off]);
                rmax[tid] = fmaxf(rmax[tid], rmax[tid + off]);
            }
            __syncthreads();
        }
        if (tid == 0) {
            float smin = rmin[0], smax = rmax[0];
            int cond = (smax > smin);
            g_smin = smin;
            g_cond = cond;
            g_ss = cond ? __fdiv_rn(__fsub_rn(smax, smin), 255.0f) : 1.0f;
            g_ctr = 0u;                   // reset for next graph replay
            __threadfence();
            g_flag = 1u;
        }
        __syncthreads();
    } else {
        if (tid == 0) {
            while (g_flag == 0u) __nanosleep(64);
            __threadfence();
        }
        __syncthreads();
    }

    const float smin = g_smin;
    const float ss   = g_ss;
    const int   cond = g_cond;

    // Per-block finalize: {1/s, deq} (64 blocks per CTA-tile)
    #pragma unroll 1
    for (int t = 0; t < NT; t++) {
        if (tid < 64) {
            float s = ssc[t][tid];
            float qv = 0.0f;
            if (cond) {
                qv = rintf(__fdiv_rn(__fsub_rn(s, smin), ss)); // half-even
                qv = fminf(fmaxf(qv, 0.0f), 255.0f);
            }
            sinfo[t][tid] = make_float2(__frcp_rn(s),
                                        __fmul_rn(qv, ss)); // smin dropped(ref)
        }
    }
    __syncthreads();

    // ========== Phase 2: re-read x (L2-resident) -> qd1 -> write ===========
    #pragma unroll 1
    for (int t = 0; t < NT; t++) {
        int chunk = (t * GRID + blockIdx.x) * 1024;
        #pragma unroll
        for (int k = 0; k < 4; k++) {
            int o = tid + k * 256;             // f4 offset: coalesced
            int g = chunk + o;
            if (g < n4) {
                float2 rd = sinfo[t][o >> 4];  // {1/s, deq} broadcast
                float4 x = __ldcg(&in4[g]);    // L2 hit (warmed in phase 1)
                float4 ov;
                ov.x = qd1(x.x, rd.x, rd.y);
                ov.y = qd1(x.y, rd.x, rd.y);
                ov.z = qd1(x.z, rd.x, rd.y);
                ov.w = qd1(x.w, rd.x, rd.y);
                __stcs(&out4[g], ov);          // stream out, don't evict x
            }
        }
    }

    // ========== Cleanup: last finisher resets flag =========================
    if (tid == 0) {
        __threadfence();
        if (atomicAdd(&g_done, 1u) == (unsigned)(gridDim.x - 1)) {
            g_done = 0u;
            g_flag = 0u;
        }
    }
}

extern "C" void kernel_launch(void* const* d_in, const int* in_sizes, int n_in,
                              void* d_out, int out_size) {
    const float* x = (const float*)d_in[0];
    float* out = (float*)d_out;
    int n = in_sizes[0];

    int n4 = n >> 2;                     // n multiple of 4 for this problem
    int num_blocks = (n + 63) >> 6;

    kFused<<<GRID, 256>>>((const float4*)x, (float4*)out, n4, num_blocks);
}

// round 13
// speedup vs baseline: 1.0217x; 1.0217x over previous
#include <cuda_runtime.h>
#include <math.h>

// x: 4096x4096 fp32 = 16,777,216 elems -> 262,144 blocks of 64.
// Single persistent kernel, 888 CTAs x 256 thr, 6 CTAs/SM resident
// (regs capped to 42 by launch_bounds; smem 20KB*6=120KB; 48 warps) =>
// exactly one wave; the spin grid-barrier cannot deadlock.
#define GRID  888
#define NT    5            // ceil(4194304 f4 / (888*1024)) = 5 tiles

__device__ float    g_pmin[GRID];
__device__ float    g_pmax[GRID];
__device__ float    g_smin;
__device__ float    g_ss;
__device__ int      g_cond;
__device__ unsigned g_ctr;            // phase-1 arrivals (returns to 0)
__device__ unsigned g_done;           // finishers       (returns to 0)
__device__ volatile unsigned g_flag;  // scales ready    (returns to 0)

// ---- Batcher selection pieces (fmax/fmin only: abs folds into FMNMX) ----
__device__ __forceinline__ void ce(float& a, float& b) {
    float hi = fmaxf(a, b);
    b = fminf(a, b);
    a = hi;
}
__device__ __forceinline__ void sort4(float& s0, float& s1, float& s2, float& s3) {
    ce(s0, s1); ce(s2, s3); ce(s0, s2); ce(s1, s3); ce(s1, s2);
}
// two sorted-desc-4 -> sorted-desc top-5 (13 ops)
__device__ __forceinline__ void merge44_top5(
    float a0, float a1, float a2, float a3,
    float b0, float b1, float b2, float b3,
    float& r0, float& r1, float& r2, float& r3, float& r4) {
    float e0 = fmaxf(a0, b0), x = fminf(a0, b0);
    float y  = fmaxf(a2, b2);
    float e1 = fmaxf(x, y),  e2 = fminf(x, y);
    float o0 = fmaxf(a1, b1), xp = fminf(a1, b1);
    float yp = fmaxf(a3, b3);
    float o1 = fmaxf(xp, yp);
    r0 = e0;
    r1 = fmaxf(o0, e1); r2 = fminf(o0, e1);
    r3 = fmaxf(o1, e2); r4 = fminf(o1, e2);
}
// two sorted-desc-5 -> sorted-desc top-5 (15 ops)
__device__ __forceinline__ void merge55_top5(
    float a0, float a1, float a2, float a3, float a4,
    float b0, float b1, float b2, float b3, float b4,
    float& r0, float& r1, float& r2, float& r3, float& r4) {
    float f0 = fmaxf(a0, b0), x = fminf(a0, b0);
    float y  = fmaxf(a4, b4);
    float f1 = fmaxf(x, y);
    float g0 = fmaxf(a2, b2);
    float e1 = fmaxf(g0, f1), e2 = fminf(g0, f1);
    float o0 = fmaxf(a1, b1), xp = fminf(a1, b1);
    float yp = fmaxf(a3, b3);
    float o1 = fmaxf(xp, yp);
    r0 = f0;
    r1 = fmaxf(o0, e1); r2 = fminf(o0, e1);
    r3 = fmaxf(o1, e2); r4 = fminf(o1, e2);
}
// two sorted-desc-5 -> ranks 3 & 4 only (10 ops)
__device__ __forceinline__ void merge55_r34(
    float a0, float a1, float a2, float a3, float a4,
    float b0, float b1, float b2, float b3, float b4,
    float& w3, float& w4) {
    float x  = fminf(a0, b0);
    float y  = fmaxf(a4, b4);
    float f1 = fmaxf(x, y);
    float g0 = fmaxf(a2, b2);
    float e2 = fminf(g0, f1);
    float xp = fminf(a1, b1);
    float yp = fmaxf(a3, b3);
    float o1 = fmaxf(xp, yp);
    w3 = fmaxf(o1, e2);
    w4 = fminf(o1, e2);
}

// quant+dequant one element (8 ops, proven): levels {0.75,1,1.5,2,3} are
// the 1-mantissa-bit fp32 grid -> clamp |q| to [0.75,3], +0x1FFFFF (round-
// half-down = positive argmin tie rule), mask. Zero if |q|<=0.375.
__device__ __forceinline__ float qd1(float x, float r, float deq) {
    float q = __fmul_rn(x, r);
    float a = fabsf(q);
    float m = fminf(fmaxf(a, 0.75f), 3.0f);
    unsigned u = (__float_as_uint(m) + 0x001FFFFFu) & 0xFFC00000u;
    float mag = (a > 0.375f) ? __uint_as_float(u) : 0.0f;
    float v = __fmul_rn(mag, deq);
    return __uint_as_float(__float_as_uint(v) |
                           (__float_as_uint(q) & 0x80000000u));
}

// XOR-swizzled slot within a warp's 128-f4 staging tile: row = f>>3 (128B),
// col = f&7 (16B granule), swizzled col = col ^ (row&7). Conflict-free for
// both the coalesced write (lane-contig f) and the 64B-stride read (f=4L+c).
__device__ __forceinline__ int sw(int f) {
    return (f & ~7) | ((f & 7) ^ ((f >> 3) & 7));
}

__global__ void __launch_bounds__(256, 6)
kFused(const float4* __restrict__ in4, float4* __restrict__ out4,
       int n4, int num_blocks) {
    __shared__ float4 sstage[8 * 128];   // 16KB: per-warp 2KB swizzled stage
    __shared__ float  ssc[NT][64];       // per-block scale s
    __shared__ float2 sinfo[NT][64];     // per-block {1/s, deq}
    __shared__ float  wmin[8], wmax[8];
    __shared__ float  rmin[256], rmax[256];
    __shared__ int    s_last;

    const int tid  = threadIdx.x;
    const int lane = tid & 31;
    const int warp = tid >> 5;
    const unsigned FULL = 0xFFFFFFFFu;

    float mn = 3.402823466e38f, mx = 0.0f;

    // ========== Phase 1: per-block scales (coalesced read via warp stage) ==
    #pragma unroll 1
    for (int t = 0; t < NT; t++) {
        int chunk = (t * GRID + blockIdx.x) * 1024;   // f4 base of CTA tile
        int wbase = chunk + warp * 128;               // warp covers 8 blocks

        __syncwarp();                                 // protect prior readers
        #pragma unroll
        for (int k = 0; k < 4; k++) {
            int f = k * 32 + lane;                    // coalesced: 512B/LDG
            int g = wbase + f;
            float4 v = (g < n4) ? __ldcg(&in4[g])
                                : make_float4(0.f, 0.f, 0.f, 0.f);
            sstage[warp * 128 + sw(f)] = v;
        }
        __syncwarp();

        float4 v0 = sstage[warp * 128 + sw(4 * lane + 0)];
        float4 v1 = sstage[warp * 128 + sw(4 * lane + 1)];
        float4 v2 = sstage[warp * 128 + sw(4 * lane + 2)];
        float4 v3 = sstage[warp * 128 + sw(4 * lane + 3)];

        float p0 = fabsf(v0.x), p1 = fabsf(v0.y), p2 = fabsf(v0.z), p3 = fabsf(v0.w);
        float q0 = fabsf(v1.x), q1 = fabsf(v1.y), q2 = fabsf(v1.z), q3 = fabsf(v1.w);
        float r0 = fabsf(v2.x), r1 = fabsf(v2.y), r2 = fabsf(v2.z), r3 = fabsf(v2.w);
        float u0 = fabsf(v3.x), u1 = fabsf(v3.y), u2 = fabsf(v3.z), u3 = fabsf(v3.w);
        sort4(p0, p1, p2, p3);
        sort4(q0, q1, q2, q3);
        sort4(r0, r1, r2, r3);
        sort4(u0, u1, u2, u3);

        float A0, A1, A2, A3, A4, B0, B1, B2, B3, B4;
        merge44_top5(p0, p1, p2, p3, q0, q1, q2, q3, A0, A1, A2, A3, A4);
        merge44_top5(r0, r1, r2, r3, u0, u1, u2, u3, B0, B1, B2, B3, B4);
        float t0, t1, t2, t3, t4;
        merge55_top5(A0, A1, A2, A3, A4, B0, B1, B2, B3, B4, t0, t1, t2, t3, t4);

        {   // cross-lane xor1: full sorted-5
            float b0 = __shfl_xor_sync(FULL, t0, 1);
            float b1 = __shfl_xor_sync(FULL, t1, 1);
            float b2 = __shfl_xor_sync(FULL, t2, 1);
            float b3 = __shfl_xor_sync(FULL, t3, 1);
            float b4 = __shfl_xor_sync(FULL, t4, 1);
            merge55_top5(t0, t1, t2, t3, t4, b0, b1, b2, b3, b4,
                         t0, t1, t2, t3, t4);
        }
        float w3, w4;
        {   // cross-lane xor2: only ranks 3 (4th largest) & 4 (5th largest)
            float b0 = __shfl_xor_sync(FULL, t0, 2);
            float b1 = __shfl_xor_sync(FULL, t1, 2);
            float b2 = __shfl_xor_sync(FULL, t2, 2);
            float b3 = __shfl_xor_sync(FULL, t3, 2);
            float b4 = __shfl_xor_sync(FULL, t4, 2);
            merge55_r34(t0, t1, t2, t3, t4, b0, b1, b2, b3, b4, w3, w4);
        }

        // jnp.quantile linear: a[59]*(1-frac)+a[60]*frac, frac=fp32(.95*63)-59
        const float FRAC = 0.95f * 63.0f - 59.0f;
        const float OMF  = 1.0f - FRAC;
        float s = __fadd_rn(__fmul_rn(w4, OMF), __fmul_rn(w3, FRAC));
        s = fmaxf(s, 1e-8f);
        if ((lane & 3) == 0) ssc[t][warp * 8 + (lane >> 2)] = s;

        int b = (chunk >> 4) + warp * 8 + (lane >> 2);
        if (b < num_blocks) { mn = fminf(mn, s); mx = fmaxf(mx, s); }
    }

    // CTA reduce min/max of scales
    #pragma unroll
    for (int m = 16; m > 0; m >>= 1) {
        mn = fminf(mn, __shfl_xor_sync(FULL, mn, m));
        mx = fmaxf(mx, __shfl_xor_sync(FULL, mx, m));
    }
    if (lane == 0) { wmin[warp] = mn; wmax[warp] = mx; }
    __syncthreads();
    if (tid == 0) {
        float cmn = wmin[0], cmx = wmax[0];
        #pragma unroll
        for (int k = 1; k < 8; k++) {
            cmn = fminf(cmn, wmin[k]);
            cmx = fmaxf(cmx, wmax[k]);
        }
        __stcg(&g_pmin[blockIdx.x], cmn);
        __stcg(&g_pmax[blockIdx.x], cmx);
        __threadfence();
        s_last = (atomicAdd(&g_ctr, 1u) == (unsigned)(gridDim.x - 1));
    }
    __syncthreads();

    // ========== Grid barrier: last CTA publishes smin/ss ===================
    if (s_last) {
        float fmn = 3.402823466e38f, fmx = 0.0f;
        for (int i = tid; i < GRID; i += 256) {
            fmn = fminf(fmn, __ldcg(&g_pmin[i]));
            fmx = fmaxf(fmx, __ldcg(&g_pmax[i]));
        }
        rmin[tid] = fmn; rmax[tid] = fmx;
        __syncthreads();
        #pragma unroll
        for (int off = 128; off > 0; off >>= 1) {
            if (tid < off) {
                rmin[tid] = fminf(rmin[tid], rmin[tid + off]);
                rmax[tid] = fmaxf(rmax[tid], rmax[tid + off]);
            }
            __syncthreads();
        }
        if (tid == 0) {
            float smin = rmin[0], smax = rmax[0];
            int cond = (smax > smin);
            g_smin = smin;
            g_cond = cond;
            g_ss = cond ? __fdiv_rn(__fsub_rn(smax, smin), 255.0f) : 1.0f;
            g_ctr = 0u;                   // reset for next graph replay
            __threadfence();
            g_flag = 1u;
        }
        __syncthreads();
    } else {
        if (tid == 0) {
            while (g_flag == 0u) __nanosleep(64);
            __threadfence();
        }
        __syncthreads();
    }

    const float smin = g_smin;
    const float ss   = g_ss;
    const int   cond = g_cond;

    // Per-block finalize: {1/s, deq} (64 blocks per CTA-tile)
    #pragma unroll 1
    for (int t = 0; t < NT; t++) {
        if (tid < 64) {
            float s = ssc[t][tid];
            float qv = 0.0f;
            if (cond) {
                qv = rintf(__fdiv_rn(__fsub_rn(s, smin), ss)); // half-even
                qv = fminf(fmaxf(qv, 0.0f), 255.0f);
            }
            sinfo[t][tid] = make_float2(__frcp_rn(s),
                                        __fmul_rn(qv, ss)); // smin dropped(ref)
        }
    }
    __syncthreads();

    // ========== Phase 2: re-read x (L2-resident) -> qd1 -> write ===========
    #pragma unroll 1
    for (int t = 0; t < NT; t++) {
        int chunk = (t * GRID + blockIdx.x) * 1024;
        #pragma unroll
        for (int k = 0; k < 4; k++) {
            int o = tid + k * 256;             // f4 offset: coalesced
            int g = chunk + o;
            if (g < n4) {
                float2 rd = sinfo[t][o >> 4];  // {1/s, deq} broadcast
                float4 x = __ldcg(&in4[g]);    // L2 hit (warmed in phase 1)
                float4 ov;
                ov.x = qd1(x.x, rd.x, rd.y);
                ov.y = qd1(x.y, rd.x, rd.y);
                ov.z = qd1(x.z, rd.x, rd.y);
                ov.w = qd1(x.w, rd.x, rd.y);
                __stcs(&out4[g], ov);          // stream out, don't evict x
            }
        }
    }

    // ========== Cleanup: last finisher resets flag =========================
    if (tid == 0) {
        __threadfence();
        if (atomicAdd(&g_done, 1u) == (unsigned)(gridDim.x - 1)) {
            g_done = 0u;
            g_flag = 0u;
        }
    }
}

extern "C" void kernel_launch(void* const* d_in, const int* in_sizes, int n_in,
                              void* d_out, int out_size) {
    const float* x = (const float*)d_in[0];
    float* out = (float*)d_out;
    int n = in_sizes[0];

    int n4 = n >> 2;                     // n multiple of 4 for this problem
    int num_blocks = (n + 63) >> 6;

    kFused<<<GRID, 256>>>((const float4*)x, (float4*)out, n4, num_blocks);
}

// round 14
// speedup vs baseline: 1.1972x; 1.1717x over previous
#include <cuda_runtime.h>
#include <math.h>

// x: 4096x4096 fp32 = 16,777,216 elems -> 262,144 blocks of 64.
// Single persistent kernel, 592 CTAs x 256 thr, 4 CTAs/SM resident
// (proven R7/R9/R11/R12) => one wave; spin grid-barrier is safe.
// cp.async double-buffered prefetch keeps DRAM saturated in both phases.
#define GRID  592
#define NT    7            // ceil(4194304 f4 / (592*1024)) = 7 tiles

__device__ float    g_pmin[GRID];
__device__ float    g_pmax[GRID];
__device__ float    g_smin;
__device__ float    g_ss;
__device__ int      g_cond;
__device__ unsigned g_ctr;            // phase-1 arrivals (returns to 0)
__device__ unsigned g_done;           // finishers       (returns to 0)
__device__ volatile unsigned g_flag;  // scales ready    (returns to 0)

// ---- Batcher selection pieces (fmax/fmin only: abs folds into FMNMX) ----
__device__ __forceinline__ void ce(float& a, float& b) {
    float hi = fmaxf(a, b);
    b = fminf(a, b);
    a = hi;
}
__device__ __forceinline__ void sort4(float& s0, float& s1, float& s2, float& s3) {
    ce(s0, s1); ce(s2, s3); ce(s0, s2); ce(s1, s3); ce(s1, s2);
}
__device__ __forceinline__ void merge44_top5(
    float a0, float a1, float a2, float a3,
    float b0, float b1, float b2, float b3,
    float& r0, float& r1, float& r2, float& r3, float& r4) {
    float e0 = fmaxf(a0, b0), x = fminf(a0, b0);
    float y  = fmaxf(a2, b2);
    float e1 = fmaxf(x, y),  e2 = fminf(x, y);
    float o0 = fmaxf(a1, b1), xp = fminf(a1, b1);
    float yp = fmaxf(a3, b3);
    float o1 = fmaxf(xp, yp);
    r0 = e0;
    r1 = fmaxf(o0, e1); r2 = fminf(o0, e1);
    r3 = fmaxf(o1, e2); r4 = fminf(o1, e2);
}
__device__ __forceinline__ void merge55_top5(
    float a0, float a1, float a2, float a3, float a4,
    float b0, float b1, float b2, float b3, float b4,
    float& r0, float& r1, float& r2, float& r3, float& r4) {
    float f0 = fmaxf(a0, b0), x = fminf(a0, b0);
    float y  = fmaxf(a4, b4);
    float f1 = fmaxf(x, y);
    float g0 = fmaxf(a2, b2);
    float e1 = fmaxf(g0, f1), e2 = fminf(g0, f1);
    float o0 = fmaxf(a1, b1), xp = fminf(a1, b1);
    float yp = fmaxf(a3, b3);
    float o1 = fmaxf(xp, yp);
    r0 = f0;
    r1 = fmaxf(o0, e1); r2 = fminf(o0, e1);
    r3 = fmaxf(o1, e2); r4 = fminf(o1, e2);
}
__device__ __forceinline__ void merge55_r34(
    float a0, float a1, float a2, float a3, float a4,
    float b0, float b1, float b2, float b3, float b4,
    float& w3, float& w4) {
    float x  = fminf(a0, b0);
    float y  = fmaxf(a4, b4);
    float f1 = fmaxf(x, y);
    float g0 = fmaxf(a2, b2);
    float e2 = fminf(g0, f1);
    float xp = fminf(a1, b1);
    float yp = fmaxf(a3, b3);
    float o1 = fmaxf(xp, yp);
    w3 = fmaxf(o1, e2);
    w4 = fminf(o1, e2);
}

// quant+dequant one element (proven): levels {0.75,1,1.5,2,3} are the
// 1-mantissa-bit fp32 grid -> clamp |q| to [0.75,3], +0x1FFFFF (round-half-
// down = positive argmin tie rule), mask. Zero if |q|<=0.375.
__device__ __forceinline__ float qd1(float x, float r, float deq) {
    float q = __fmul_rn(x, r);
    float a = fabsf(q);
    float m = fminf(fmaxf(a, 0.75f), 3.0f);
    unsigned u = (__float_as_uint(m) + 0x001FFFFFu) & 0xFFC00000u;
    float mag = (a > 0.375f) ? __uint_as_float(u) : 0.0f;
    float v = __fmul_rn(mag, deq);
    return __uint_as_float(__float_as_uint(v) |
                           (__float_as_uint(q) & 0x80000000u));
}

// XOR-swizzle for phase-1 stage: conflict-free for coalesced write (f
// lane-contig) AND 64B-stride read (f = 4L+c).
__device__ __forceinline__ int sw(int f) {
    return (f & ~7) | ((f & 7) ^ ((f >> 3) & 7));
}

__global__ void __launch_bounds__(256, 4)
kFused(const float4* __restrict__ in4, float4* __restrict__ out4,
       int n4, int num_blocks) {
    // double-buffered per-warp stage: 8 warps x 2 bufs x 128 f4 = 32KB
    __shared__ float4 sstage[8 * 256];
    __shared__ float  ssc[NT][64];       // per-block scale s
    __shared__ float2 sinfo[NT][64];     // per-block {1/s, deq}
    __shared__ float  wmin[8], wmax[8];
    __shared__ float  rmin[256], rmax[256];
    __shared__ int    s_last;

    const int tid  = threadIdx.x;
    const int lane = tid & 31;
    const int warp = tid >> 5;
    const unsigned FULL = 0xFFFFFFFFu;
    const float4 z = make_float4(0.f, 0.f, 0.f, 0.f);

    unsigned sbase;
    asm("{ .reg .u64 t; cvta.to.shared.u64 t, %1; cvt.u32.u64 %0, t; }"
        : "=r"(sbase) : "l"(sstage));

    float mn = 3.402823466e38f, mx = 0.0f;

    // ---- phase-1 prefetch: swizzled dst, cp.async.cg (L2-only) ----
    auto issue1 = [&](int t) {
        int wbase = (t * GRID + blockIdx.x) * 1024 + warp * 128;
        int boff  = warp * 256 + (t & 1) * 128;
        #pragma unroll
        for (int k = 0; k < 4; k++) {
            int f = k * 32 + lane;
            int g = wbase + f;
            if (g < n4) {
                unsigned dst = sbase + (unsigned)(boff + sw(f)) * 16u;
                asm volatile("cp.async.cg.shared.global [%0], [%1], 16;"
                             :: "r"(dst), "l"(in4 + g));
            } else {
                sstage[boff + sw(f)] = z;
            }
        }
        asm volatile("cp.async.commit_group;");
    };

    // ========== Phase 1: per-block scales (pipelined read) =================
    issue1(0);
    #pragma unroll 1
    for (int t = 0; t < NT; t++) {
        if (t + 1 < NT) {
            issue1(t + 1);
            asm volatile("cp.async.wait_group 1;");
        } else {
            asm volatile("cp.async.wait_group 0;");
        }
        __syncwarp();

        const float4* buf = &sstage[warp * 256 + (t & 1) * 128];
        float4 v0 = buf[sw(4 * lane + 0)];
        float4 v1 = buf[sw(4 * lane + 1)];
        float4 v2 = buf[sw(4 * lane + 2)];
        float4 v3 = buf[sw(4 * lane + 3)];

        float p0 = fabsf(v0.x), p1 = fabsf(v0.y), p2 = fabsf(v0.z), p3 = fabsf(v0.w);
        float q0 = fabsf(v1.x), q1 = fabsf(v1.y), q2 = fabsf(v1.z), q3 = fabsf(v1.w);
        float r0 = fabsf(v2.x), r1 = fabsf(v2.y), r2 = fabsf(v2.z), r3 = fabsf(v2.w);
        float u0 = fabsf(v3.x), u1 = fabsf(v3.y), u2 = fabsf(v3.z), u3 = fabsf(v3.w);
        sort4(p0, p1, p2, p3);
        sort4(q0, q1, q2, q3);
        sort4(r0, r1, r2, r3);
        sort4(u0, u1, u2, u3);

        float A0, A1, A2, A3, A4, B0, B1, B2, B3, B4;
        merge44_top5(p0, p1, p2, p3, q0, q1, q2, q3, A0, A1, A2, A3, A4);
        merge44_top5(r0, r1, r2, r3, u0, u1, u2, u3, B0, B1, B2, B3, B4);
        float t0, t1, t2, t3, t4;
        merge55_top5(A0, A1, A2, A3, A4, B0, B1, B2, B3, B4, t0, t1, t2, t3, t4);

        {   // cross-lane xor1: full sorted-5
            float b0 = __shfl_xor_sync(FULL, t0, 1);
            float b1 = __shfl_xor_sync(FULL, t1, 1);
            float b2 = __shfl_xor_sync(FULL, t2, 1);
            float b3 = __shfl_xor_sync(FULL, t3, 1);
            float b4 = __shfl_xor_sync(FULL, t4, 1);
            merge55_top5(t0, t1, t2, t3, t4, b0, b1, b2, b3, b4,
                         t0, t1, t2, t3, t4);
        }
        float w3, w4;
        {   // cross-lane xor2: ranks 3 (4th largest) & 4 (5th largest)
            float b0 = __shfl_xor_sync(FULL, t0, 2);
            float b1 = __shfl_xor_sync(FULL, t1, 2);
            float b2 = __shfl_xor_sync(FULL, t2, 2);
            float b3 = __shfl_xor_sync(FULL, t3, 2);
            float b4 = __shfl_xor_sync(FULL, t4, 2);
            merge55_r34(t0, t1, t2, t3, t4, b0, b1, b2, b3, b4, w3, w4);
        }

        // jnp.quantile linear: a[59]*(1-frac)+a[60]*frac, frac=fp32(.95*63)-59
        const float FRAC = 0.95f * 63.0f - 59.0f;
        const float OMF  = 1.0f - FRAC;
        float s = __fadd_rn(__fmul_rn(w4, OMF), __fmul_rn(w3, FRAC));
        s = fmaxf(s, 1e-8f);
        if ((lane & 3) == 0) ssc[t][warp * 8 + (lane >> 2)] = s;

        int b = ((t * GRID + blockIdx.x) * 1024 >> 4) + warp * 8 + (lane >> 2);
        if (b < num_blocks) { mn = fminf(mn, s); mx = fmaxf(mx, s); }
    }

    // CTA reduce min/max of scales
    #pragma unroll
    for (int m = 16; m > 0; m >>= 1) {
        mn = fminf(mn, __shfl_xor_sync(FULL, mn, m));
        mx = fmaxf(mx, __shfl_xor_sync(FULL, mx, m));
    }
    if (lane == 0) { wmin[warp] = mn; wmax[warp] = mx; }
    __syncthreads();
    if (tid == 0) {
        float cmn = wmin[0], cmx = wmax[0];
        #pragma unroll
        for (int k = 1; k < 8; k++) {
            cmn = fminf(cmn, wmin[k]);
            cmx = fmaxf(cmx, wmax[k]);
        }
        __stcg(&g_pmin[blockIdx.x], cmn);
        __stcg(&g_pmax[blockIdx.x], cmx);
        __threadfence();
        s_last = (atomicAdd(&g_ctr, 1u) == (unsigned)(gridDim.x - 1));
    }
    __syncthreads();

    // ========== Grid barrier: last CTA publishes smin/ss ===================
    if (s_last) {
        float fmn = 3.402823466e38f, fmx = 0.0f;
        for (int i = tid; i < GRID; i += 256) {
            fmn = fminf(fmn, __ldcg(&g_pmin[i]));
            fmx = fmaxf(fmx, __ldcg(&g_pmax[i]));
        }
        rmin[tid] = fmn; rmax[tid] = fmx;
        __syncthreads();
        #pragma unroll
        for (int off = 128; off > 0; off >>= 1) {
            if (tid < off) {
                rmin[tid] = fminf(rmin[tid], rmin[tid + off]);
                rmax[tid] = fmaxf(rmax[tid], rmax[tid + off]);
            }
            __syncthreads();
        }
        if (tid == 0) {
            float smin = rmin[0], smax = rmax[0];
            int cond = (smax > smin);
            g_smin = smin;
            g_cond = cond;
            g_ss = cond ? __fdiv_rn(__fsub_rn(smax, smin), 255.0f) : 1.0f;
            g_ctr = 0u;                   // reset for next graph replay
            __threadfence();
            g_flag = 1u;
        }
        __syncthreads();
    } else {
        if (tid == 0) {
            while (g_flag == 0u) __nanosleep(64);
            __threadfence();
        }
        __syncthreads();
    }

    const float smin = g_smin;
    const float ss   = g_ss;
    const int   cond = g_cond;

    // Per-block finalize: {1/s, deq} (64 blocks per CTA-tile)
    #pragma unroll 1
    for (int t = 0; t < NT; t++) {
        if (tid < 64) {
            float s = ssc[t][tid];
            float qv = 0.0f;
            if (cond) {
                qv = rintf(__fdiv_rn(__fsub_rn(s, smin), ss)); // half-even
                qv = fminf(fmaxf(qv, 0.0f), 255.0f);
            }
            sinfo[t][tid] = make_float2(__frcp_rn(s),
                                        __fmul_rn(qv, ss)); // smin dropped(ref)
        }
    }
    __syncthreads();

    // ---- phase-2 prefetch: linear dst (lane reads own contiguous 64B) ----
    auto issue2 = [&](int t) {
        int wbase = (t * GRID + blockIdx.x) * 1024 + warp * 128;
        int boff  = warp * 256 + (t & 1) * 128;
        #pragma unroll
        for (int k = 0; k < 4; k++) {
            int f = k * 32 + lane;
            int g = wbase + f;
            if (g < n4) {
                unsigned dst = sbase + (unsigned)(boff + f) * 16u;
                asm volatile("cp.async.cg.shared.global [%0], [%1], 16;"
                             :: "r"(dst), "l"(in4 + g));
            }
        }
        asm volatile("cp.async.commit_group;");
    };

    // ========== Phase 2: staged re-read (L2) -> qd1 -> coalesced write =====
    issue2(0);
    #pragma unroll 1
    for (int t = 0; t < NT; t++) {
        if (t + 1 < NT) {
            issue2(t + 1);
            asm volatile("cp.async.wait_group 1;");
        } else {
            asm volatile("cp.async.wait_group 0;");
        }
        __syncwarp();

        int wbase = (t * GRID + blockIdx.x) * 1024 + warp * 128;
        const float4* buf = &sstage[warp * 256 + (t & 1) * 128];
        #pragma unroll
        for (int k = 0; k < 4; k++) {
            int f = k * 32 + lane;
            int g = wbase + f;
            if (g < n4) {
                float2 rd = sinfo[t][(warp * 128 + f) >> 4];
                float4 x = buf[f];
                float4 ov;
                ov.x = qd1(x.x, rd.x, rd.y);
                ov.y = qd1(x.y, rd.x, rd.y);
                ov.z = qd1(x.z, rd.x, rd.y);
                ov.w = qd1(x.w, rd.x, rd.y);
                __stcs(&out4[g], ov);
            }
        }
        __syncwarp();   // all lanes done reading buf before next overwrite
    }

    // ========== Cleanup: last finisher resets flag =========================
    if (tid == 0) {
        __threadfence();
        if (atomicAdd(&g_done, 1u) == (unsigned)(gridDim.x - 1)) {
            g_done = 0u;
            g_flag = 0u;
        }
    }
}

extern "C" void kernel_launch(void* const* d_in, const int* in_sizes, int n_in,
                              void* d_out, int out_size) {
    const float* x = (const float*)d_in[0];
    float* out = (float*)d_out;
    int n = in_sizes[0];

    int n4 = n >> 2;                     // n multiple of 4 for this problem
    int num_blocks = (n + 63) >> 6;

    kFused<<<GRID, 256>>>((const float4*)x, (float4*)out, n4, num_blocks);
}

// round 15
// speedup vs baseline: 1.2070x; 1.0082x over previous
#include <cuda_runtime.h>
#include <math.h>

// x: 4096x4096 fp32 = 16,777,216 elems -> 262,144 blocks of 64.
// Single persistent kernel, 740 CTAs x 256 thr, 5 CTAs/SM resident
// (regs capped 51, smem ~39.5KB*5=198KB<=228KB, 40 warps) => exactly one
// wave; the spin grid-barrier cannot deadlock.
// cp.async double-buffered prefetch keeps DRAM streaming in both phases.
#define GRID  740
#define NT    6            // ceil(4194304 f4 / (740*1024)) = 6 tiles

__device__ float    g_pmin[GRID];
__device__ float    g_pmax[GRID];
__device__ float    g_smin;
__device__ float    g_ss;
__device__ int      g_cond;
__device__ unsigned g_ctr;            // phase-1 arrivals (returns to 0)
__device__ unsigned g_done;           // finishers       (returns to 0)
__device__ volatile unsigned g_flag;  // scales ready    (returns to 0)

// ---- Batcher selection pieces (fmax/fmin only: abs folds into FMNMX) ----
__device__ __forceinline__ void ce(float& a, float& b) {
    float hi = fmaxf(a, b);
    b = fminf(a, b);
    a = hi;
}
__device__ __forceinline__ void sort4(float& s0, float& s1, float& s2, float& s3) {
    ce(s0, s1); ce(s2, s3); ce(s0, s2); ce(s1, s3); ce(s1, s2);
}
__device__ __forceinline__ void merge44_top5(
    float a0, float a1, float a2, float a3,
    float b0, float b1, float b2, float b3,
    float& r0, float& r1, float& r2, float& r3, float& r4) {
    float e0 = fmaxf(a0, b0), x = fminf(a0, b0);
    float y  = fmaxf(a2, b2);
    float e1 = fmaxf(x, y),  e2 = fminf(x, y);
    float o0 = fmaxf(a1, b1), xp = fminf(a1, b1);
    float yp = fmaxf(a3, b3);
    float o1 = fmaxf(xp, yp);
    r0 = e0;
    r1 = fmaxf(o0, e1); r2 = fminf(o0, e1);
    r3 = fmaxf(o1, e2); r4 = fminf(o1, e2);
}
__device__ __forceinline__ void merge55_top5(
    float a0, float a1, float a2, float a3, float a4,
    float b0, float b1, float b2, float b3, float b4,
    float& r0, float& r1, float& r2, float& r3, float& r4) {
    float f0 = fmaxf(a0, b0), x = fminf(a0, b0);
    float y  = fmaxf(a4, b4);
    float f1 = fmaxf(x, y);
    float g0 = fmaxf(a2, b2);
    float e1 = fmaxf(g0, f1), e2 = fminf(g0, f1);
    float o0 = fmaxf(a1, b1), xp = fminf(a1, b1);
    float yp = fmaxf(a3, b3);
    float o1 = fmaxf(xp, yp);
    r0 = f0;
    r1 = fmaxf(o0, e1); r2 = fminf(o0, e1);
    r3 = fmaxf(o1, e2); r4 = fminf(o1, e2);
}
__device__ __forceinline__ void merge55_r34(
    float a0, float a1, float a2, float a3, float a4,
    float b0, float b1, float b2, float b3, float b4,
    float& w3, float& w4) {
    float x  = fminf(a0, b0);
    float y  = fmaxf(a4, b4);
    float f1 = fmaxf(x, y);
    float g0 = fmaxf(a2, b2);
    float e2 = fminf(g0, f1);
    float xp = fminf(a1, b1);
    float yp = fmaxf(a3, b3);
    float o1 = fmaxf(xp, yp);
    w3 = fmaxf(o1, e2);
    w4 = fminf(o1, e2);
}

// quant+dequant one element (proven): levels {0.75,1,1.5,2,3} are the
// 1-mantissa-bit fp32 grid -> clamp |q| to [0.75,3], +0x1FFFFF (round-half-
// down = positive argmin tie rule), mask. Zero if |q|<=0.375.
__device__ __forceinline__ float qd1(float x, float r, float deq) {
    float q = __fmul_rn(x, r);
    float a = fabsf(q);
    float m = fminf(fmaxf(a, 0.75f), 3.0f);
    unsigned u = (__float_as_uint(m) + 0x001FFFFFu) & 0xFFC00000u;
    float mag = (a > 0.375f) ? __uint_as_float(u) : 0.0f;
    float v = __fmul_rn(mag, deq);
    return __uint_as_float(__float_as_uint(v) |
                           (__float_as_uint(q) & 0x80000000u));
}

// XOR-swizzle for phase-1 stage: conflict-free for coalesced write (f
// lane-contig) AND 64B-stride read (f = 4L+c).
__device__ __forceinline__ int sw(int f) {
    return (f & ~7) | ((f & 7) ^ ((f >> 3) & 7));
}

__global__ void __launch_bounds__(256, 5)
kFused(const float4* __restrict__ in4, float4* __restrict__ out4,
       int n4, int num_blocks) {
    // double-buffered per-warp stage: 8 warps x 2 bufs x 128 f4 = 32KB
    __shared__ float4 sstage[8 * 256];
    __shared__ float  ssc[NT][64];       // per-block scale s
    __shared__ float2 sinfo[NT][64];     // per-block {1/s, deq}
    __shared__ float  wmin[8], wmax[8];
    __shared__ float  rmin[256], rmax[256];
    __shared__ int    s_last;

    const int tid  = threadIdx.x;
    const int lane = tid & 31;
    const int warp = tid >> 5;
    const unsigned FULL = 0xFFFFFFFFu;
    const float4 z = make_float4(0.f, 0.f, 0.f, 0.f);

    unsigned sbase;
    asm("{ .reg .u64 t; cvta.to.shared.u64 t, %1; cvt.u32.u64 %0, t; }"
        : "=r"(sbase) : "l"(sstage));

    float mn = 3.402823466e38f, mx = 0.0f;

    // ---- phase-1 prefetch: swizzled dst, cp.async.cg ----
    auto issue1 = [&](int t) {
        int wbase = (t * GRID + blockIdx.x) * 1024 + warp * 128;
        int boff  = warp * 256 + (t & 1) * 128;
        #pragma unroll
        for (int k = 0; k < 4; k++) {
            int f = k * 32 + lane;
            int g = wbase + f;
            if (g < n4) {
                unsigned dst = sbase + (unsigned)(boff + sw(f)) * 16u;
                asm volatile("cp.async.cg.shared.global [%0], [%1], 16;"
                             :: "r"(dst), "l"(in4 + g));
            } else {
                sstage[boff + sw(f)] = z;
            }
        }
        asm volatile("cp.async.commit_group;");
    };

    // ========== Phase 1: per-block scales (pipelined read) =================
    issue1(0);
    #pragma unroll 1
    for (int t = 0; t < NT; t++) {
        if (t + 1 < NT) {
            issue1(t + 1);
            asm volatile("cp.async.wait_group 1;");
        } else {
            asm volatile("cp.async.wait_group 0;");
        }
        __syncwarp();

        const float4* buf = &sstage[warp * 256 + (t & 1) * 128];
        float4 v0 = buf[sw(4 * lane + 0)];
        float4 v1 = buf[sw(4 * lane + 1)];
        float4 v2 = buf[sw(4 * lane + 2)];
        float4 v3 = buf[sw(4 * lane + 3)];

        float p0 = fabsf(v0.x), p1 = fabsf(v0.y), p2 = fabsf(v0.z), p3 = fabsf(v0.w);
        float q0 = fabsf(v1.x), q1 = fabsf(v1.y), q2 = fabsf(v1.z), q3 = fabsf(v1.w);
        float r0 = fabsf(v2.x), r1 = fabsf(v2.y), r2 = fabsf(v2.z), r3 = fabsf(v2.w);
        float u0 = fabsf(v3.x), u1 = fabsf(v3.y), u2 = fabsf(v3.z), u3 = fabsf(v3.w);
        sort4(p0, p1, p2, p3);
        sort4(q0, q1, q2, q3);
        sort4(r0, r1, r2, r3);
        sort4(u0, u1, u2, u3);

        float A0, A1, A2, A3, A4, B0, B1, B2, B3, B4;
        merge44_top5(p0, p1, p2, p3, q0, q1, q2, q3, A0, A1, A2, A3, A4);
        merge44_top5(r0, r1, r2, r3, u0, u1, u2, u3, B0, B1, B2, B3, B4);
        float t0, t1, t2, t3, t4;
        merge55_top5(A0, A1, A2, A3, A4, B0, B1, B2, B3, B4, t0, t1, t2, t3, t4);

        {   // cross-lane xor1: full sorted-5
            float b0 = __shfl_xor_sync(FULL, t0, 1);
            float b1 = __shfl_xor_sync(FULL, t1, 1);
            float b2 = __shfl_xor_sync(FULL, t2, 1);
            float b3 = __shfl_xor_sync(FULL, t3, 1);
            float b4 = __shfl_xor_sync(FULL, t4, 1);
            merge55_top5(t0, t1, t2, t3, t4, b0, b1, b2, b3, b4,
                         t0, t1, t2, t3, t4);
        }
        float w3, w4;
        {   // cross-lane xor2: ranks 3 (4th largest) & 4 (5th largest)
            float b0 = __shfl_xor_sync(FULL, t0, 2);
            float b1 = __shfl_xor_sync(FULL, t1, 2);
            float b2 = __shfl_xor_sync(FULL, t2, 2);
            float b3 = __shfl_xor_sync(FULL, t3, 2);
            float b4 = __shfl_xor_sync(FULL, t4, 2);
            merge55_r34(t0, t1, t2, t3, t4, b0, b1, b2, b3, b4, w3, w4);
        }

        // jnp.quantile linear: a[59]*(1-frac)+a[60]*frac, frac=fp32(.95*63)-59
        const float FRAC = 0.95f * 63.0f - 59.0f;
        const float OMF  = 1.0f - FRAC;
        float s = __fadd_rn(__fmul_rn(w4, OMF), __fmul_rn(w3, FRAC));
        s = fmaxf(s, 1e-8f);
        if ((lane & 3) == 0) ssc[t][warp * 8 + (lane >> 2)] = s;

        int b = ((t * GRID + blockIdx.x) * 1024 >> 4) + warp * 8 + (lane >> 2);
        if (b < num_blocks) { mn = fminf(mn, s); mx = fmaxf(mx, s); }
    }

    // CTA reduce min/max of scales
    #pragma unroll
    for (int m = 16; m > 0; m >>= 1) {
        mn = fminf(mn, __shfl_xor_sync(FULL, mn, m));
        mx = fmaxf(mx, __shfl_xor_sync(FULL, mx, m));
    }
    if (lane == 0) { wmin[warp] = mn; wmax[warp] = mx; }
    __syncthreads();
    if (tid == 0) {
        float cmn = wmin[0], cmx = wmax[0];
        #pragma unroll
        for (int k = 1; k < 8; k++) {
            cmn = fminf(cmn, wmin[k]);
            cmx = fmaxf(cmx, wmax[k]);
        }
        __stcg(&g_pmin[blockIdx.x], cmn);
        __stcg(&g_pmax[blockIdx.x], cmx);
        __threadfence();
        s_last = (atomicAdd(&g_ctr, 1u) == (unsigned)(gridDim.x - 1));
    }
    __syncthreads();

    // ========== Grid barrier: last CTA publishes smin/ss ===================
    if (s_last) {
        float fmn = 3.402823466e38f, fmx = 0.0f;
        for (int i = tid; i < GRID; i += 256) {
            fmn = fminf(fmn, __ldcg(&g_pmin[i]));
            fmx = fmaxf(fmx, __ldcg(&g_pmax[i]));
        }
        rmin[tid] = fmn; rmax[tid] = fmx;
        __syncthreads();
        #pragma unroll
        for (int off = 128; off > 0; off >>= 1) {
            if (tid < off) {
                rmin[tid] = fminf(rmin[tid], rmin[tid + off]);
                rmax[tid] = fmaxf(rmax[tid], rmax[tid + off]);
            }
            __syncthreads();
        }
        if (tid == 0) {
            float smin = rmin[0], smax = rmax[0];
            int cond = (smax > smin);
            g_smin = smin;
            g_cond = cond;
            g_ss = cond ? __fdiv_rn(__fsub_rn(smax, smin), 255.0f) : 1.0f;
            g_ctr = 0u;                   // reset for next graph replay
            __threadfence();
            g_flag = 1u;
        }
        __syncthreads();
    } else {
        if (tid == 0) {
            while (g_flag == 0u) __nanosleep(64);
            __threadfence();
        }
        __syncthreads();
    }

    const float smin = g_smin;
    const float ss   = g_ss;
    const int   cond = g_cond;

    // Per-block finalize: {1/s, deq} (64 blocks per CTA-tile)
    #pragma unroll 1
    for (int t = 0; t < NT; t++) {
        if (tid < 64) {
            float s = ssc[t][tid];
            float qv = 0.0f;
            if (cond) {
                qv = rintf(__fdiv_rn(__fsub_rn(s, smin), ss)); // half-even
                qv = fminf(fmaxf(qv, 0.0f), 255.0f);
            }
            sinfo[t][tid] = make_float2(__frcp_rn(s),
                                        __fmul_rn(qv, ss)); // smin dropped(ref)
        }
    }
    __syncthreads();

    // ---- phase-2 prefetch: linear dst (lane reads own contiguous 64B) ----
    auto issue2 = [&](int t) {
        int wbase = (t * GRID + blockIdx.x) * 1024 + warp * 128;
        int boff  = warp * 256 + (t & 1) * 128;
        #pragma unroll
        for (int k = 0; k < 4; k++) {
            int f = k * 32 + lane;
            int g = wbase + f;
            if (g < n4) {
                unsigned dst = sbase + (unsigned)(boff + f) * 16u;
                asm volatile("cp.async.cg.shared.global [%0], [%1], 16;"
                             :: "r"(dst), "l"(in4 + g));
            }
        }
        asm volatile("cp.async.commit_group;");
    };

    // ========== Phase 2: staged re-read (L2) -> qd1 -> coalesced write =====
    issue2(0);
    #pragma unroll 1
    for (int t = 0; t < NT; t++) {
        if (t + 1 < NT) {
            issue2(t + 1);
            asm volatile("cp.async.wait_group 1;");
        } else {
            asm volatile("cp.async.wait_group 0;");
        }
        __syncwarp();

        int wbase = (t * GRID + blockIdx.x) * 1024 + warp * 128;
        const float4* buf = &sstage[warp * 256 + (t & 1) * 128];
        #pragma unroll
        for (int k = 0; k < 4; k++) {
            int f = k * 32 + lane;
            int g = wbase + f;
            if (g < n4) {
                float2 rd = sinfo[t][(warp * 128 + f) >> 4];
                float4 x = buf[f];
                float4 ov;
                ov.x = qd1(x.x, rd.x, rd.y);
                ov.y = qd1(x.y, rd.x, rd.y);
                ov.z = qd1(x.z, rd.x, rd.y);
                ov.w = qd1(x.w, rd.x, rd.y);
                __stcs(&out4[g], ov);
            }
        }
        __syncwarp();   // all lanes done reading buf before next overwrite
    }

    // ========== Cleanup: last finisher resets flag =========================
    if (tid == 0) {
        __threadfence();
        if (atomicAdd(&g_done, 1u) == (unsigned)(gridDim.x - 1)) {
            g_done = 0u;
            g_flag = 0u;
        }
    }
}

extern "C" void kernel_launch(void* const* d_in, const int* in_sizes, int n_in,
                              void* d_out, int out_size) {
    const float* x = (const float*)d_in[0];
    float* out = (float*)d_out;
    int n = in_sizes[0];

    int n4 = n >> 2;                     // n multiple of 4 for this problem
    int num_blocks = (n + 63) >> 6;

    kFused<<<GRID, 256>>>((const float4*)x, (float4*)out, n4, num_blocks);
}